// round 11
// baseline (speedup 1.0000x reference)
#include <cuda_runtime.h>
#include <cuda_bf16.h>
#include <stdint.h>

// Problem constants
#define KS   16          // S
#define KN   1024        // N
#define KEPS 1e-7f

// Scratch: y[s][j][c*128+b] bf16 (16 MiB), base[s][i][b] fp32 (8 MiB),
//          wb[a][cb=c*128+b] bf16 (128 KiB)
__device__ __align__(16) __nv_bfloat16 g_y[(size_t)KS * KN * 512];
__device__ __align__(16) float         g_base[(size_t)KS * KN * 128];
__device__ __align__(16) __nv_bfloat16 g_wb[(size_t)128 * 512];

// ---------------------------------------------------------------- helpers
static __device__ __forceinline__ uint32_t smem_u32(const void* p) {
    return (uint32_t)__cvta_generic_to_shared(p);
}
static __device__ __forceinline__ void ldsm_x4(uint32_t* r, uint32_t addr) {
    asm volatile("ldmatrix.sync.aligned.m8n8.x4.shared.b16 {%0,%1,%2,%3}, [%4];\n"
                 : "=r"(r[0]), "=r"(r[1]), "=r"(r[2]), "=r"(r[3]) : "r"(addr));
}
static __device__ __forceinline__ void ldsm_x4_t(uint32_t* r, uint32_t addr) {
    asm volatile("ldmatrix.sync.aligned.m8n8.x4.trans.shared.b16 {%0,%1,%2,%3}, [%4];\n"
                 : "=r"(r[0]), "=r"(r[1]), "=r"(r[2]), "=r"(r[3]) : "r"(addr));
}
static __device__ __forceinline__ void mma_bf16(float* d, const uint32_t* a,
                                                uint32_t b0, uint32_t b1) {
    asm volatile("mma.sync.aligned.m16n8k16.row.col.f32.bf16.bf16.f32 "
                 "{%0,%1,%2,%3}, {%4,%5,%6,%7}, {%8,%9}, {%0,%1,%2,%3};\n"
                 : "+f"(d[0]), "+f"(d[1]), "+f"(d[2]), "+f"(d[3])
                 : "r"(a[0]), "r"(a[1]), "r"(a[2]), "r"(a[3]), "r"(b0), "r"(b1));
}
static __device__ __forceinline__ uint32_t pack2f(float lo, float hi) {
    uint32_t d;
    asm("cvt.rn.bf16x2.f32 %0, %1, %2;\n" : "=r"(d) : "f"(hi), "f"(lo));
    return d;
}
static __device__ __forceinline__ void cp_async16(uint32_t dst, const void* src) {
    asm volatile("cp.async.cg.shared.global [%0], [%1], 16;\n"
                 :: "r"(dst), "l"(src) : "memory");
}
#define CP_COMMIT() asm volatile("cp.async.commit_group;\n" ::: "memory")
template <int N>
static __device__ __forceinline__ void cp_wait() {
    asm volatile("cp.async.wait_group %0;\n" :: "n"(N) : "memory");
}

// ================================================================ WCONV
// g_wb[a*512 + c*128 + b] = bf16(w[a*512 + b*4 + c])
__global__ __launch_bounds__(256) void wconv_kernel(const float* __restrict__ w)
{
    int t = blockIdx.x * 256 + threadIdx.x;     // 0..65535
    int a = t >> 9;
    int cb = t & 511;
    int c = cb >> 7, b = cb & 127;
    g_wb[t] = __float2bfloat16_rn(w[(size_t)a * 512 + b * 4 + c]);
}

// ================================================================ AUX (fused)
// Blocks [0, 1024): prep  — g_y[row=(s*N+j), cb] = sum_a x[row,a]*wb[a,cb]
// Blocks [1024, 1280): base — g_base = x @ theta, full fp32 SIMT
__global__ __launch_bounds__(256) void aux_kernel(
    const float* __restrict__ x, const float* __restrict__ th)
{
    const int tid  = threadIdx.x;
    const int lane = tid & 31;
    const int warp = tid >> 5;

    if (blockIdx.x < 1024) {
        // ---------------- PREP ----------------
        __shared__ __nv_bfloat16 Xs[64][24];    // [j][a(16)], pad->24
        __shared__ __nv_bfloat16 Ws[16][136];   // [a][cb(128)], pad->136

        const int wm = warp >> 2;           // 0..1 -> 32 j rows
        const int wn = warp & 3;            // 0..3 -> 32 cb cols
        const int row0 = (blockIdx.x >> 2) * 64;
        const int col0 = (blockIdx.x & 3) * 128;

        float acc[2][4][4];
#pragma unroll
        for (int mi = 0; mi < 2; mi++)
#pragma unroll
            for (int ni = 0; ni < 4; ni++)
#pragma unroll
                for (int e = 0; e < 4; e++) acc[mi][ni][e] = 0.f;

        for (int a0 = 0; a0 < 128; a0 += 16) {
            {   // X tile: 64 rows x 16 a = 256 float4s, 1 per thread
                int r = tid >> 2, fo = tid & 3;
                float4 v = *reinterpret_cast<const float4*>(
                    x + (size_t)(row0 + r) * 128 + a0 + fo * 4);
                *reinterpret_cast<uint32_t*>(&Xs[r][fo * 4 + 0]) = pack2f(v.x, v.y);
                *reinterpret_cast<uint32_t*>(&Xs[r][fo * 4 + 2]) = pack2f(v.z, v.w);
            }
            {   // W tile: 16 a x 128 cb = 2048 bf16, 1 uint4 per thread
                int al = tid >> 4;
                int ch = (tid & 15) * 8;
                *reinterpret_cast<uint4*>(&Ws[al][ch]) =
                    *reinterpret_cast<const uint4*>(g_wb + (size_t)(a0 + al) * 512 + col0 + ch);
            }
            __syncthreads();

            uint32_t af[2][4], bfr[2][4];
#pragma unroll
            for (int mi = 0; mi < 2; mi++)
                ldsm_x4(af[mi], smem_u32(&Xs[wm * 32 + mi * 16 + (lane & 15)][(lane >> 4) * 8]));
#pragma unroll
            for (int nh = 0; nh < 2; nh++)
                ldsm_x4_t(bfr[nh], smem_u32(&Ws[lane & 15][wn * 32 + nh * 16 + (lane >> 4) * 8]));
#pragma unroll
            for (int mi = 0; mi < 2; mi++)
#pragma unroll
                for (int ni = 0; ni < 4; ni++)
                    mma_bf16(acc[mi][ni], af[mi],
                             bfr[ni >> 1][(ni & 1) * 2], bfr[ni >> 1][(ni & 1) * 2 + 1]);
            __syncthreads();
        }

        const int g  = lane >> 2;
        const int qc = lane & 3;
#pragma unroll
        for (int mi = 0; mi < 2; mi++)
#pragma unroll
            for (int ni = 0; ni < 4; ni++)
#pragma unroll
                for (int h = 0; h < 2; h++) {
                    int r  = row0 + wm * 32 + mi * 16 + g + h * 8;
                    int cg = col0 + wn * 32 + ni * 8 + qc * 2;
                    *reinterpret_cast<uint32_t*>(&g_y[(size_t)r * 512 + cg]) =
                        pack2f(acc[mi][ni][h * 2 + 0], acc[mi][ni][h * 2 + 1]);
                }
    } else {
        // ---------------- BASE (fp32 exact) ----------------
        __shared__ float Xf[64][32];
        __shared__ float Ts[32][128];

        const int tr   = warp;              // 8 warps x 8 rows
        const int row0 = (blockIdx.x - 1024) * 64;

        float acc[8][4];
#pragma unroll
        for (int i = 0; i < 8; i++)
#pragma unroll
            for (int m = 0; m < 4; m++) acc[i][m] = 0.f;

        for (int k0 = 0; k0 < 128; k0 += 32) {
#pragma unroll
            for (int q = 0; q < 2; q++) {
                int u = tid + q * 256;
                int r = u >> 3, f = u & 7;
                *reinterpret_cast<float4*>(&Xf[r][f * 4]) =
                    *reinterpret_cast<const float4*>(x + (size_t)(row0 + r) * 128 + k0 + f * 4);
            }
#pragma unroll
            for (int q = 0; q < 4; q++) {
                int u  = tid + q * 256;
                int kk = u >> 5, cf = u & 31;
                *reinterpret_cast<float4*>(&Ts[kk][cf * 4]) =
                    *reinterpret_cast<const float4*>(th + (size_t)(k0 + kk) * 128 + cf * 4);
            }
            __syncthreads();

#pragma unroll 4
            for (int kk = 0; kk < 32; kk++) {
                float ts[4];
#pragma unroll
                for (int m = 0; m < 4; m++) ts[m] = Ts[kk][lane + 32 * m];
#pragma unroll
                for (int i = 0; i < 8; i++) {
                    float xs = Xf[tr * 8 + i][kk];
#pragma unroll
                    for (int m = 0; m < 4; m++) acc[i][m] = fmaf(xs, ts[m], acc[i][m]);
                }
            }
            __syncthreads();
        }

#pragma unroll
        for (int i = 0; i < 8; i++)
#pragma unroll
            for (int m = 0; m < 4; m++)
                g_base[(size_t)(row0 + tr * 8 + i) * 128 + lane + 32 * m] = acc[i][m];
    }
}

// ================================================================ MAIN
// 512 threads, 64 i-rows x 128 b per CTA, k-tile = 32 j, ONE barrier per kt.
// As double-buffered (2 stages), Ys 4-stage cp.async ring (prefetch dist 3,
// wait<2> so y(kt+1) is resident before the barrier at the end of iter kt).
// smem (dynamic):
//   As   2 x [4c x 64i x (32j pad->40) bf16] = 40960 B
//   Ys   4 x [4c x 32j x (128b pad->136) bf16] = 139264 B
//   inv  4c x 64 fp32 = 1024 B
#define AS_OFF   0
#define AS_STG   20480
#define YS_OFF   40960
#define YS_STG   34816
#define INV_OFF  180224
#define SMEM_TOT 181248

static __device__ __forceinline__ uint32_t ys_off(int stage, int c, int j, int b) {
    return YS_OFF + stage * YS_STG + (((c * 32 + j) * 136) + b) * 2;
}

__global__ __launch_bounds__(512, 1) void main_kernel(
    const float* __restrict__ A, float* __restrict__ out)
{
    extern __shared__ char smem[];
    const uint32_t sb = smem_u32(smem);

    const int tid  = threadIdx.x;
    const int lane = tid & 31;
    const int warp = tid >> 5;
    const int wm = warp >> 3;     // 0..1 -> 32 i rows
    const int wn = warp & 7;      // 0..7 -> 16 b cols
    const int s  = blockIdx.y;
    const int i0 = blockIdx.x * 64;

    const int il = tid >> 3;      // 0..63 : i row this thread converts
    const int jg = tid & 7;       // 0..7  : j-group of 4 within the 32-j k-tile

    const float* Ap = A + (size_t)(s * KN + i0 + il) * 5120 + jg * 20;

    // Y cp.async thread mapping (fixed per thread): u = tid + q*512
    //   j = u>>6, c = (u&63)>>4, bq = u&15
    float acc[4][2][2][4];
#pragma unroll
    for (int c = 0; c < 4; c++)
#pragma unroll
        for (int mi = 0; mi < 2; mi++)
#pragma unroll
            for (int ni = 0; ni < 2; ni++)
#pragma unroll
                for (int e = 0; e < 4; e++) acc[c][mi][ni][e] = 0.f;

    float rs[4] = {0.f, 0.f, 0.f, 0.f};
    uint4 qa[5];

    // -- pipeline helpers (inlined) --
    auto issue_y = [&](int kt2) {
        if (kt2 < 32) {
#pragma unroll
            for (int q = 0; q < 4; q++) {
                int u = tid + q * 512;
                int j = u >> 6, rem = u & 63;
                int c = rem >> 4, bq = rem & 15;
                cp_async16(sb + ys_off(kt2 & 3, c, j, bq * 8),
                           g_y + (size_t)(s * KN + kt2 * 32 + j) * 512 + c * 128 + bq * 8);
            }
        }
        CP_COMMIT();
    };
    auto load_qa = [&](int kt2) {
        const uint4* an = reinterpret_cast<const uint4*>(Ap + (size_t)kt2 * 160);
#pragma unroll
        for (int p = 0; p < 5; p++) qa[p] = __ldcs(an + p);
    };
    auto conv_store = [&](int kt2) {
        float f[20];
#pragma unroll
        for (int p = 0; p < 5; p++) {
            f[p * 4 + 0] = __uint_as_float(qa[p].x);
            f[p * 4 + 1] = __uint_as_float(qa[p].y);
            f[p * 4 + 2] = __uint_as_float(qa[p].z);
            f[p * 4 + 3] = __uint_as_float(qa[p].w);
        }
        const int ab = (kt2 & 1) * AS_STG;
#pragma unroll
        for (int c = 0; c < 4; c++) {
            rs[c] += (f[c] + f[5 + c]) + (f[10 + c] + f[15 + c]);
            uint2 v;
            v.x = pack2f(f[c],      f[5 + c]);
            v.y = pack2f(f[10 + c], f[15 + c]);
            *reinterpret_cast<uint2*>(smem + AS_OFF + ab + (c * 64 + il) * 80 + jg * 8) = v;
        }
    };

    // -- prologue: stages y0..y2 in flight, A(0) converted, A(1) in regs --
    issue_y(0);
    issue_y(1);
    issue_y(2);
    load_qa(0);
    conv_store(0);
    load_qa(1);
    cp_wait<2>();          // y(0) resident
    __syncthreads();

    for (int kt = 0; kt < 32; kt++) {
        // 1) keep the Y ring full (stage (kt+3)&3; empty commit past the end)
        issue_y(kt + 3);

        // 2) convert A(kt+1) into the other As buffer; prefetch A(kt+2)
        if (kt + 1 < 32) {
            conv_store(kt + 1);
            if (kt + 2 < 32) load_qa(kt + 2);
        }

        // 3) mma(kt): As stage kt&1, Ys stage kt&3 (both barrier-protected)
        const int ab  = (kt & 1) * AS_STG;
        const int yst = kt & 3;
#pragma unroll
        for (int c = 0; c < 4; c++) {
#pragma unroll
            for (int ks = 0; ks < 2; ks++) {
                uint32_t af[2][4], bfr[4];
#pragma unroll
                for (int mi = 0; mi < 2; mi++)
                    ldsm_x4(af[mi], sb + AS_OFF + ab
                            + (c * 64 + wm * 32 + mi * 16 + (lane & 15)) * 80
                            + (ks * 16 + (lane >> 4) * 8) * 2);
                ldsm_x4_t(bfr, sb + ys_off(yst, c, ks * 16 + (lane & 15),
                                           wn * 16 + (lane >> 4) * 8));
#pragma unroll
                for (int mi = 0; mi < 2; mi++)
#pragma unroll
                    for (int ni = 0; ni < 2; ni++)
                        mma_bf16(acc[c][mi][ni], af[mi], bfr[ni * 2], bfr[ni * 2 + 1]);
            }
        }

        // 4) ensure y(kt+1) landed, then the single barrier
        cp_wait<2>();
        __syncthreads();
    }

    // ---- rowsums -> inv norm (jg spans lane bits 0..2) ----
#pragma unroll
    for (int c = 0; c < 4; c++) {
        rs[c] += __shfl_xor_sync(0xFFFFFFFFu, rs[c], 1);
        rs[c] += __shfl_xor_sync(0xFFFFFFFFu, rs[c], 2);
        rs[c] += __shfl_xor_sync(0xFFFFFFFFu, rs[c], 4);
    }
    float* inv = reinterpret_cast<float*>(smem + INV_OFF);
    if (jg == 0) {
#pragma unroll
        for (int c = 0; c < 4; c++) inv[c * 64 + il] = 1.0f / (rs[c] + KEPS);
    }
    __syncthreads();

    // ---- epilogue ----
    const int g  = lane >> 2;
    const int qc = lane & 3;
#pragma unroll
    for (int mi = 0; mi < 2; mi++)
#pragma unroll
        for (int h = 0; h < 2; h++) {
            const int rl = wm * 32 + mi * 16 + g + h * 8;
            float iv[4];
#pragma unroll
            for (int c = 0; c < 4; c++) iv[c] = inv[c * 64 + rl];
#pragma unroll
            for (int ni = 0; ni < 2; ni++) {
                const int b = wn * 16 + ni * 8 + qc * 2;
                float v0 = 0.f, v1 = 0.f;
#pragma unroll
                for (int c = 0; c < 4; c++) {
                    v0 = fmaf(acc[c][mi][ni][h * 2 + 0], iv[c], v0);
                    v1 = fmaf(acc[c][mi][ni][h * 2 + 1], iv[c], v1);
                }
                const size_t o = (size_t)(s * KN + i0 + rl) * 128 + b;
                v0 += g_base[o];
                v1 += g_base[o + 1];
                out[o]     = tanhf(v0);
                out[o + 1] = tanhf(v1);
            }
        }
}

// ================================================================ launch
extern "C" void kernel_launch(void* const* d_in, const int* in_sizes, int n_in,
                              void* d_out, int out_size) {
    const float* A  = (const float*)d_in[0];
    const float* x  = (const float*)d_in[1];
    const float* w  = (const float*)d_in[2];
    const float* th = (const float*)d_in[3];
    float* out = (float*)d_out;
    (void)in_sizes; (void)n_in; (void)out_size;

    cudaFuncSetAttribute(main_kernel, cudaFuncAttributeMaxDynamicSharedMemorySize, SMEM_TOT);

    wconv_kernel<<<256, 256>>>(w);
    aux_kernel<<<1280, 256>>>(x, th);
    main_kernel<<<dim3(16, 16), 512, SMEM_TOT>>>(A, out);
}